// round 3
// baseline (speedup 1.0000x reference)
#include <cuda_runtime.h>

#define NB 16384
#define NSTEPS 100
#define DTC 0.01f
#define SQDT 0.1f
#define SIG0 0.5f

typedef unsigned long long u64;

// packed f32x2 helpers (FFMA2 — only reachable via PTX)
#define FMA2(d, a, b, c) \
    asm("fma.rn.f32x2 %0, %1, %2, %3;" : "=l"(d) : "l"(a), "l"(b), "l"(c))
#define PACK2(d, lo, hi) \
    asm("mov.b64 %0, {%1, %2};" : "=l"(d) : "r"(lo), "r"(hi))
#define UNPACK2(lo, hi, d) \
    asm("mov.b64 {%0, %1}, %2;" : "=r"(lo), "=r"(hi) : "l"(d))

// Shared-memory layout per MLP (float offsets)
#define OFF_A    0            // W1 row 0 (t weights) [64]
#define OFF_C    64           // W1 row 1 (y weights) [64]
#define OFF_B1   128          // b1 [64]
#define OFF_B2   192          // b2 [64]
#define OFF_W3T  256          // W3 transposed [3][64]
#define OFF_B3   448          // [4]
#define OFF_W2   456          // [k=0..63][j=0..7][h=0..1][4]  (pair-interleaved)
#define MLP_FLOATS (456 + 4096)   // 4552 floats, 16B-aligned stride

__device__ float g_partials[128];
__device__ unsigned int g_count = 0;

__global__ __launch_bounds__(128) void bsde_kernel(
    const float* __restrict__ y0, const float* __restrict__ Y0,
    const float* __restrict__ zW1, const float* __restrict__ zb1,
    const float* __restrict__ zW2, const float* __restrict__ zb2,
    const float* __restrict__ zW3, const float* __restrict__ zb3,
    const float* __restrict__ qW1, const float* __restrict__ qb1,
    const float* __restrict__ qW2, const float* __restrict__ qb2,
    const float* __restrict__ qW3, const float* __restrict__ qb3,
    const float* __restrict__ dW, const float* __restrict__ dZ,
    float* __restrict__ out)
{
    __shared__ float smw[2 * MLP_FLOATS];
    __shared__ float red[128];
    __shared__ int is_last;
    const int tx = threadIdx.x;

    // ---- Stage weights. W2 layout: [k][j][h][4] so the lane-pair's two
    // 16B loads sit in the SAME 128B line (1 smem wavefront, not 2). ----
    for (int idx = tx; idx < 4096; idx += 128) {
        int k = idx >> 6, n = idx & 63;
        int hh = n >> 5, r = n & 31, j = r >> 2, c = r & 3;
        int dst = OFF_W2 + k * 64 + j * 8 + hh * 4 + c;
        smw[dst] = zW2[idx];
        smw[MLP_FLOATS + dst] = qW2[idx];
    }
    if (tx < 64) {
        int n = tx;
        smw[OFF_A + n]  = zW1[n];
        smw[OFF_C + n]  = zW1[64 + n];
        smw[OFF_B1 + n] = zb1[n];
        smw[OFF_B2 + n] = zb2[n];
        smw[OFF_W3T + 0 * 64 + n] = zW3[n * 3 + 0];
        smw[OFF_W3T + 1 * 64 + n] = zW3[n * 3 + 1];
        smw[OFF_W3T + 2 * 64 + n] = zW3[n * 3 + 2];
        smw[MLP_FLOATS + OFF_A + n]  = qW1[n];
        smw[MLP_FLOATS + OFF_C + n]  = qW1[64 + n];
        smw[MLP_FLOATS + OFF_B1 + n] = qb1[n];
        smw[MLP_FLOATS + OFF_B2 + n] = qb2[n];
        smw[MLP_FLOATS + OFF_W3T + 0 * 64 + n] = qW3[n];
        smw[MLP_FLOATS + OFF_W3T + 1 * 64 + n] = 0.f;
        smw[MLP_FLOATS + OFF_W3T + 2 * 64 + n] = 0.f;
    }
    if (tx < 4) {
        smw[OFF_B3 + tx] = (tx < 3) ? zb3[tx] : 0.f;
        smw[MLP_FLOATS + OFF_B3 + tx] = (tx == 0) ? qb3[0] : 0.f;
    }
    __syncthreads();

    // ---- Lane pair (h=0,1) cooperates on TWO paths (a, b). ----
    const int tid  = blockIdx.x * 128 + tx;
    const int pair = tid >> 1;          // 0..8191
    const int h    = tid & 1;

    const float y00 = y0[0], Y00 = Y0[0];
    float ya = y00, yb = y00, Ya = Y00, Yb = Y00;
    float t = 0.f, loss = 0.f;
    const float* dWp = dW + pair * 6;   // path a = pair*2, path b = pair*2+1
    const float* dZp = dZ + pair * 6;

    #pragma unroll 1
    for (int i = 0; i < NSTEPS; ++i) {
        float dwa0 = dWp[0] * SQDT, dwa1 = dWp[1] * SQDT, dwa2 = dWp[2] * SQDT;
        float dwb0 = dWp[3] * SQDT, dwb1 = dWp[4] * SQDT, dwb2 = dWp[5] * SQDT;
        float dza0 = dZp[0] * SQDT, dza1 = dZp[1] * SQDT, dza2 = dZp[2] * SQDT;
        float dzb0 = dZp[3] * SQDT, dzb1 = dZp[4] * SQDT, dzb2 = dZp[5] * SQDT;
        dWp += NB * 3; dZp += NB * 3;

        float zdwa = 0.f, zdza = 0.f, zdwb = 0.f, zdzb = 0.f, qa = 0.f, qb = 0.f;

        #pragma unroll 1
        for (int m = 0; m < 2; ++m) {          // m=0: z-MLP, m=1: q-MLP
            const float* Wm = smw + m * MLP_FLOATS;

            // 16 packed accumulators per path (this lane's 32 neurons)
            u64 acc0[16], acc1[16];
            const float* b2p = Wm + OFF_B2 + h * 32;
            #pragma unroll
            for (int u = 0; u < 16; ++u) {
                u64 b = *(const u64*)(b2p + 2 * u);
                acc0[u] = b;
                acc1[u] = b;
            }

            // fused layer1(JIT) + layer2
            #pragma unroll 2
            for (int k = 0; k < 64; ++k) {
                float ak = Wm[OFF_A + k];
                float ck = Wm[OFF_C + k];
                float bk = Wm[OFF_B1 + k];
                float h1a = fmaxf(fmaf(t, ak, fmaf(ya, ck, bk)), 0.f);
                float h1b = fmaxf(fmaf(t, ak, fmaf(yb, ck, bk)), 0.f);
                u64 ha, hb;
                unsigned int hab = __float_as_uint(h1a), hbb = __float_as_uint(h1b);
                PACK2(ha, hab, hab);
                PACK2(hb, hbb, hbb);
                const ulonglong2* wk = (const ulonglong2*)(Wm + OFF_W2 + k * 64 + h * 4);
                #pragma unroll
                for (int j = 0; j < 8; ++j) {
                    ulonglong2 w = wk[2 * j];    // stride between chunks = 8 floats
                    FMA2(acc0[2 * j],     ha, w.x, acc0[2 * j]);
                    FMA2(acc0[2 * j + 1], ha, w.y, acc0[2 * j + 1]);
                    FMA2(acc1[2 * j],     hb, w.x, acc1[2 * j]);
                    FMA2(acc1[2 * j + 1], hb, w.y, acc1[2 * j + 1]);
                }
            }

            // layer 3 (packed, W3 transposed; weight loads shared by both paths)
            const float* w3c0 = Wm + OFF_W3T + 0 * 64 + h * 32;
            const float* w3c1 = Wm + OFF_W3T + 1 * 64 + h * 32;
            const float* w3c2 = Wm + OFF_W3T + 2 * 64 + h * 32;
            u64 oa0 = 0ull, oa1 = 0ull, oa2 = 0ull;
            u64 ob0 = 0ull, ob1 = 0ull, ob2 = 0ull;
            #pragma unroll
            for (int u = 0; u < 16; ++u) {
                u64 w0 = *(const u64*)(w3c0 + 2 * u);
                u64 w1 = *(const u64*)(w3c1 + 2 * u);
                u64 w2v = *(const u64*)(w3c2 + 2 * u);
                unsigned int lo, hi;
                UNPACK2(lo, hi, acc0[u]);
                float f0 = fmaxf(__uint_as_float(lo), 0.f);
                float f1 = fmaxf(__uint_as_float(hi), 0.f);
                u64 hp;
                PACK2(hp, __float_as_uint(f0), __float_as_uint(f1));
                FMA2(oa0, hp, w0, oa0);
                FMA2(oa1, hp, w1, oa1);
                FMA2(oa2, hp, w2v, oa2);
                UNPACK2(lo, hi, acc1[u]);
                f0 = fmaxf(__uint_as_float(lo), 0.f);
                f1 = fmaxf(__uint_as_float(hi), 0.f);
                PACK2(hp, __float_as_uint(f0), __float_as_uint(f1));
                FMA2(ob0, hp, w0, ob0);
                FMA2(ob1, hp, w1, ob1);
                FMA2(ob2, hp, w2v, ob2);
            }
            float oA0, oA1, oA2, oB0, oB1, oB2;
            {
                unsigned int lo, hi;
                UNPACK2(lo, hi, oa0); oA0 = __uint_as_float(lo) + __uint_as_float(hi);
                UNPACK2(lo, hi, oa1); oA1 = __uint_as_float(lo) + __uint_as_float(hi);
                UNPACK2(lo, hi, oa2); oA2 = __uint_as_float(lo) + __uint_as_float(hi);
                UNPACK2(lo, hi, ob0); oB0 = __uint_as_float(lo) + __uint_as_float(hi);
                UNPACK2(lo, hi, ob1); oB1 = __uint_as_float(lo) + __uint_as_float(hi);
                UNPACK2(lo, hi, ob2); oB2 = __uint_as_float(lo) + __uint_as_float(hi);
            }
            // combine the pair's halves, add bias
            oA0 += __shfl_xor_sync(0xffffffffu, oA0, 1);
            oA1 += __shfl_xor_sync(0xffffffffu, oA1, 1);
            oA2 += __shfl_xor_sync(0xffffffffu, oA2, 1);
            oB0 += __shfl_xor_sync(0xffffffffu, oB0, 1);
            oB1 += __shfl_xor_sync(0xffffffffu, oB1, 1);
            oB2 += __shfl_xor_sync(0xffffffffu, oB2, 1);
            float bb0 = Wm[OFF_B3 + 0], bb1 = Wm[OFF_B3 + 1], bb2 = Wm[OFF_B3 + 2];
            oA0 += bb0; oA1 += bb1; oA2 += bb2;
            oB0 += bb0; oB1 += bb1; oB2 += bb2;

            if (m == 0) {
                zdwa = oA0 * dwa0 + oA1 * dwa1 + oA2 * dwa2;
                zdza = oA0 * dza0 + oA1 * dza1 + oA2 * dza2;
                zdwb = oB0 * dwb0 + oB1 * dwb1 + oB2 * dwb2;
                zdzb = oB0 * dzb0 + oB1 * dzb1 + oB2 * dzb2;
            } else {
                qa = oA0;
                qb = oB0;
            }
        }

        // SDE / BSDE update (residual = z.dw - z.dz; Y cancels)
        float fa = 0.5f * qa * qa, fb = 0.5f * qb * qb;
        ya = ya + qa * DTC + SIG0 * (dwa0 + dwa1 + dwa2);
        yb = yb + qb * DTC + SIG0 * (dwb0 + dwb1 + dwb2);
        Ya = Ya - fa * DTC + zdwa;
        Yb = Yb - fb * DTC + zdwb;
        float ra = zdwa - zdza, rb = zdwb - zdzb;
        loss = fmaf(ra, ra, loss);
        loss = fmaf(rb, rb, loss);
        t += DTC;
    }
    float ta2 = Ya - ya * ya;
    float tb2 = Yb - yb * yb;
    loss = fmaf(ta2, ta2, loss);
    loss = fmaf(tb2, tb2, loss);     // duplicated across lane pair -> 0.5 scale below

    // ---- block reduction ----
    red[tx] = loss;
    __syncthreads();
    #pragma unroll
    for (int s = 64; s > 0; s >>= 1) {
        if (tx < s) red[tx] += red[tx + s];
        __syncthreads();
    }
    if (tx == 0) {
        g_partials[blockIdx.x] = red[0];
        __threadfence();
        unsigned int prev = atomicAdd(&g_count, 1u);
        is_last = (prev == gridDim.x - 1) ? 1 : 0;
    }
    __syncthreads();

    // ---- last block: final deterministic reduction + counter reset ----
    if (is_last) {
        __threadfence();
        red[tx] = g_partials[tx];     // gridDim.x == blockDim.x == 128
        __syncthreads();
        #pragma unroll
        for (int s = 64; s > 0; s >>= 1) {
            if (tx < s) red[tx] += red[tx + s];
            __syncthreads();
        }
        if (tx == 0) {
            out[0] = red[0] * (0.5f / (float)NB);
            g_count = 0;              // reset for next graph replay
        }
    }
}

extern "C" void kernel_launch(void* const* d_in, const int* in_sizes, int n_in,
                              void* d_out, int out_size)
{
    const float* y0  = (const float*)d_in[0];
    const float* Y0  = (const float*)d_in[1];
    const float* zW1 = (const float*)d_in[2];
    const float* zb1 = (const float*)d_in[3];
    const float* zW2 = (const float*)d_in[4];
    const float* zb2 = (const float*)d_in[5];
    const float* zW3 = (const float*)d_in[6];
    const float* zb3 = (const float*)d_in[7];
    const float* qW1 = (const float*)d_in[8];
    const float* qb1 = (const float*)d_in[9];
    const float* qW2 = (const float*)d_in[10];
    const float* qb2 = (const float*)d_in[11];
    const float* qW3 = (const float*)d_in[12];
    const float* qb3 = (const float*)d_in[13];
    const float* dW  = (const float*)d_in[14];
    const float* dZ  = (const float*)d_in[15];

    bsde_kernel<<<128, 128>>>(y0, Y0, zW1, zb1, zW2, zb2, zW3, zb3,
                              qW1, qb1, qW2, qb2, qW3, qb3, dW, dZ,
                              (float*)d_out);
}

// round 4
// speedup vs baseline: 1.0035x; 1.0035x over previous
#include <cuda_runtime.h>

#define NB 16384
#define NSTEPS 100
#define DTC 0.01f
#define SQDT 0.1f
#define SIG0 0.5f

typedef unsigned long long u64;

// packed f32x2 helpers (FFMA2 — only reachable via PTX)
#define FMA2(d, a, b, c) \
    asm("fma.rn.f32x2 %0, %1, %2, %3;" : "=l"(d) : "l"(a), "l"(b), "l"(c))
#define PACK2(d, lo, hi) \
    asm("mov.b64 %0, {%1, %2};" : "=l"(d) : "r"(lo), "r"(hi))
#define UNPACK2(lo, hi, d) \
    asm("mov.b64 {%0, %1}, %2;" : "=r"(lo), "=r"(hi) : "l"(d))

// Shared-memory layout per MLP (float offsets)
#define OFF_A    0            // W1 row 0 (t weights) [64]
#define OFF_C    64           // W1 row 1 (y weights) [64]
#define OFF_B1   128          // b1 [64]
#define OFF_B2   192          // b2 [64]
#define OFF_W3T  256          // W3 transposed [3][64]
#define OFF_B3   448          // [4]
#define OFF_W2   456          // [k=0..63][j=0..7][h=0..1][4]  (pair-interleaved)
#define MLP_FLOATS (456 + 4096)   // 4552 floats, 16B-aligned stride

__device__ float g_partials[128];
__device__ unsigned int g_count = 0;

__global__ __launch_bounds__(128) void bsde_kernel(
    const float* __restrict__ y0, const float* __restrict__ Y0,
    const float* __restrict__ zW1, const float* __restrict__ zb1,
    const float* __restrict__ zW2, const float* __restrict__ zb2,
    const float* __restrict__ zW3, const float* __restrict__ zb3,
    const float* __restrict__ qW1, const float* __restrict__ qb1,
    const float* __restrict__ qW2, const float* __restrict__ qb2,
    const float* __restrict__ qW3, const float* __restrict__ qb3,
    const float* __restrict__ dW, const float* __restrict__ dZ,
    float* __restrict__ out)
{
    __shared__ float smw[2 * MLP_FLOATS];
    __shared__ float red[128];
    __shared__ int is_last;
    const int tx = threadIdx.x;

    // ---- Stage weights. W2 layout: [k][j][h][4] so the lane-pair's two
    // 16B loads sit in the SAME 128B line (1 smem wavefront, not 2). ----
    for (int idx = tx; idx < 4096; idx += 128) {
        int k = idx >> 6, n = idx & 63;
        int hh = n >> 5, r = n & 31, j = r >> 2, c = r & 3;
        int dst = OFF_W2 + k * 64 + j * 8 + hh * 4 + c;
        smw[dst] = zW2[idx];
        smw[MLP_FLOATS + dst] = qW2[idx];
    }
    if (tx < 64) {
        int n = tx;
        smw[OFF_A + n]  = zW1[n];
        smw[OFF_C + n]  = zW1[64 + n];
        smw[OFF_B1 + n] = zb1[n];
        smw[OFF_B2 + n] = zb2[n];
        smw[OFF_W3T + 0 * 64 + n] = zW3[n * 3 + 0];
        smw[OFF_W3T + 1 * 64 + n] = zW3[n * 3 + 1];
        smw[OFF_W3T + 2 * 64 + n] = zW3[n * 3 + 2];
        smw[MLP_FLOATS + OFF_A + n]  = qW1[n];
        smw[MLP_FLOATS + OFF_C + n]  = qW1[64 + n];
        smw[MLP_FLOATS + OFF_B1 + n] = qb1[n];
        smw[MLP_FLOATS + OFF_B2 + n] = qb2[n];
        smw[MLP_FLOATS + OFF_W3T + 0 * 64 + n] = qW3[n];
        smw[MLP_FLOATS + OFF_W3T + 1 * 64 + n] = 0.f;
        smw[MLP_FLOATS + OFF_W3T + 2 * 64 + n] = 0.f;
    }
    if (tx < 4) {
        smw[OFF_B3 + tx] = (tx < 3) ? zb3[tx] : 0.f;
        smw[MLP_FLOATS + OFF_B3 + tx] = (tx == 0) ? qb3[0] : 0.f;
    }
    __syncthreads();

    // ---- Lane pair (h=0,1) cooperates on TWO paths (a, b). ----
    const int tid  = blockIdx.x * 128 + tx;
    const int pair = tid >> 1;          // 0..8191
    const int h    = tid & 1;

    const float y00 = y0[0], Y00 = Y0[0];
    float ya = y00, yb = y00, Ya = Y00, Yb = Y00;
    float t = 0.f, loss = 0.f;
    const float* dWp = dW + pair * 6;   // path a = pair*2, path b = pair*2+1
    const float* dZp = dZ + pair * 6;

    #pragma unroll 1
    for (int i = 0; i < NSTEPS; ++i) {
        float dwa0 = dWp[0] * SQDT, dwa1 = dWp[1] * SQDT, dwa2 = dWp[2] * SQDT;
        float dwb0 = dWp[3] * SQDT, dwb1 = dWp[4] * SQDT, dwb2 = dWp[5] * SQDT;
        float dza0 = dZp[0] * SQDT, dza1 = dZp[1] * SQDT, dza2 = dZp[2] * SQDT;
        float dzb0 = dZp[3] * SQDT, dzb1 = dZp[4] * SQDT, dzb2 = dZp[5] * SQDT;
        dWp += NB * 3; dZp += NB * 3;

        float zdwa = 0.f, zdza = 0.f, zdwb = 0.f, zdzb = 0.f, qa = 0.f, qb = 0.f;

        #pragma unroll 1
        for (int m = 0; m < 2; ++m) {          // m=0: z-MLP, m=1: q-MLP
            const float* Wm = smw + m * MLP_FLOATS;

            // 16 packed accumulators per path (this lane's 32 neurons)
            u64 acc0[16], acc1[16];
            const float* b2p = Wm + OFF_B2 + h * 32;
            #pragma unroll
            for (int u = 0; u < 16; ++u) {
                u64 b = *(const u64*)(b2p + 2 * u);
                acc0[u] = b;
                acc1[u] = b;
            }

            // fused layer1(JIT) + layer2
            #pragma unroll 2
            for (int k = 0; k < 64; ++k) {
                float ak = Wm[OFF_A + k];
                float ck = Wm[OFF_C + k];
                float bk = Wm[OFF_B1 + k];
                float h1a = fmaxf(fmaf(t, ak, fmaf(ya, ck, bk)), 0.f);
                float h1b = fmaxf(fmaf(t, ak, fmaf(yb, ck, bk)), 0.f);
                u64 ha, hb;
                unsigned int hab = __float_as_uint(h1a), hbb = __float_as_uint(h1b);
                PACK2(ha, hab, hab);
                PACK2(hb, hbb, hbb);
                const ulonglong2* wk = (const ulonglong2*)(Wm + OFF_W2 + k * 64 + h * 4);
                #pragma unroll
                for (int j = 0; j < 8; ++j) {
                    ulonglong2 w = wk[2 * j];    // stride between chunks = 8 floats
                    FMA2(acc0[2 * j],     ha, w.x, acc0[2 * j]);
                    FMA2(acc0[2 * j + 1], ha, w.y, acc0[2 * j + 1]);
                    FMA2(acc1[2 * j],     hb, w.x, acc1[2 * j]);
                    FMA2(acc1[2 * j + 1], hb, w.y, acc1[2 * j + 1]);
                }
            }

            // layer 3 (packed, W3 transposed; weight loads shared by both paths)
            const float* w3c0 = Wm + OFF_W3T + 0 * 64 + h * 32;
            const float* w3c1 = Wm + OFF_W3T + 1 * 64 + h * 32;
            const float* w3c2 = Wm + OFF_W3T + 2 * 64 + h * 32;
            u64 oa0 = 0ull, oa1 = 0ull, oa2 = 0ull;
            u64 ob0 = 0ull, ob1 = 0ull, ob2 = 0ull;
            #pragma unroll
            for (int u = 0; u < 16; ++u) {
                u64 w0 = *(const u64*)(w3c0 + 2 * u);
                u64 w1 = *(const u64*)(w3c1 + 2 * u);
                u64 w2v = *(const u64*)(w3c2 + 2 * u);
                unsigned int lo, hi;
                UNPACK2(lo, hi, acc0[u]);
                float f0 = fmaxf(__uint_as_float(lo), 0.f);
                float f1 = fmaxf(__uint_as_float(hi), 0.f);
                u64 hp;
                PACK2(hp, __float_as_uint(f0), __float_as_uint(f1));
                FMA2(oa0, hp, w0, oa0);
                FMA2(oa1, hp, w1, oa1);
                FMA2(oa2, hp, w2v, oa2);
                UNPACK2(lo, hi, acc1[u]);
                f0 = fmaxf(__uint_as_float(lo), 0.f);
                f1 = fmaxf(__uint_as_float(hi), 0.f);
                PACK2(hp, __float_as_uint(f0), __float_as_uint(f1));
                FMA2(ob0, hp, w0, ob0);
                FMA2(ob1, hp, w1, ob1);
                FMA2(ob2, hp, w2v, ob2);
            }
            float oA0, oA1, oA2, oB0, oB1, oB2;
            {
                unsigned int lo, hi;
                UNPACK2(lo, hi, oa0); oA0 = __uint_as_float(lo) + __uint_as_float(hi);
                UNPACK2(lo, hi, oa1); oA1 = __uint_as_float(lo) + __uint_as_float(hi);
                UNPACK2(lo, hi, oa2); oA2 = __uint_as_float(lo) + __uint_as_float(hi);
                UNPACK2(lo, hi, ob0); oB0 = __uint_as_float(lo) + __uint_as_float(hi);
                UNPACK2(lo, hi, ob1); oB1 = __uint_as_float(lo) + __uint_as_float(hi);
                UNPACK2(lo, hi, ob2); oB2 = __uint_as_float(lo) + __uint_as_float(hi);
            }
            // combine the pair's halves, add bias
            oA0 += __shfl_xor_sync(0xffffffffu, oA0, 1);
            oA1 += __shfl_xor_sync(0xffffffffu, oA1, 1);
            oA2 += __shfl_xor_sync(0xffffffffu, oA2, 1);
            oB0 += __shfl_xor_sync(0xffffffffu, oB0, 1);
            oB1 += __shfl_xor_sync(0xffffffffu, oB1, 1);
            oB2 += __shfl_xor_sync(0xffffffffu, oB2, 1);
            float bb0 = Wm[OFF_B3 + 0], bb1 = Wm[OFF_B3 + 1], bb2 = Wm[OFF_B3 + 2];
            oA0 += bb0; oA1 += bb1; oA2 += bb2;
            oB0 += bb0; oB1 += bb1; oB2 += bb2;

            if (m == 0) {
                zdwa = oA0 * dwa0 + oA1 * dwa1 + oA2 * dwa2;
                zdza = oA0 * dza0 + oA1 * dza1 + oA2 * dza2;
                zdwb = oB0 * dwb0 + oB1 * dwb1 + oB2 * dwb2;
                zdzb = oB0 * dzb0 + oB1 * dzb1 + oB2 * dzb2;
            } else {
                qa = oA0;
                qb = oB0;
            }
        }

        // SDE / BSDE update (residual = z.dw - z.dz; Y cancels)
        float fa = 0.5f * qa * qa, fb = 0.5f * qb * qb;
        ya = ya + qa * DTC + SIG0 * (dwa0 + dwa1 + dwa2);
        yb = yb + qb * DTC + SIG0 * (dwb0 + dwb1 + dwb2);
        Ya = Ya - fa * DTC + zdwa;
        Yb = Yb - fb * DTC + zdwb;
        float ra = zdwa - zdza, rb = zdwb - zdzb;
        loss = fmaf(ra, ra, loss);
        loss = fmaf(rb, rb, loss);
        t += DTC;
    }
    float ta2 = Ya - ya * ya;
    float tb2 = Yb - yb * yb;
    loss = fmaf(ta2, ta2, loss);
    loss = fmaf(tb2, tb2, loss);     // duplicated across lane pair -> 0.5 scale below

    // ---- block reduction ----
    red[tx] = loss;
    __syncthreads();
    #pragma unroll
    for (int s = 64; s > 0; s >>= 1) {
        if (tx < s) red[tx] += red[tx + s];
        __syncthreads();
    }
    if (tx == 0) {
        g_partials[blockIdx.x] = red[0];
        __threadfence();
        unsigned int prev = atomicAdd(&g_count, 1u);
        is_last = (prev == gridDim.x - 1) ? 1 : 0;
    }
    __syncthreads();

    // ---- last block: final deterministic reduction + counter reset ----
    if (is_last) {
        __threadfence();
        red[tx] = g_partials[tx];     // gridDim.x == blockDim.x == 128
        __syncthreads();
        #pragma unroll
        for (int s = 64; s > 0; s >>= 1) {
            if (tx < s) red[tx] += red[tx + s];
            __syncthreads();
        }
        if (tx == 0) {
            out[0] = red[0] * (0.5f / (float)NB);
            g_count = 0;              // reset for next graph replay
        }
    }
}

extern "C" void kernel_launch(void* const* d_in, const int* in_sizes, int n_in,
                              void* d_out, int out_size)
{
    const float* y0  = (const float*)d_in[0];
    const float* Y0  = (const float*)d_in[1];
    const float* zW1 = (const float*)d_in[2];
    const float* zb1 = (const float*)d_in[3];
    const float* zW2 = (const float*)d_in[4];
    const float* zb2 = (const float*)d_in[5];
    const float* zW3 = (const float*)d_in[6];
    const float* zb3 = (const float*)d_in[7];
    const float* qW1 = (const float*)d_in[8];
    const float* qb1 = (const float*)d_in[9];
    const float* qW2 = (const float*)d_in[10];
    const float* qb2 = (const float*)d_in[11];
    const float* qW3 = (const float*)d_in[12];
    const float* qb3 = (const float*)d_in[13];
    const float* dW  = (const float*)d_in[14];
    const float* dZ  = (const float*)d_in[15];

    bsde_kernel<<<128, 128>>>(y0, Y0, zW1, zb1, zW2, zb2, zW3, zb3,
                              qW1, qb1, qW2, qb2, qW3, qb3, dW, dZ,
                              (float*)d_out);
}

// round 7
// speedup vs baseline: 2.2435x; 2.2355x over previous
#include <cuda_runtime.h>
#include <cuda_bf16.h>

#define NB 16384
#define NSTEPS 100
#define DTC 0.01f
#define SQDT 0.1f
#define SIG0 0.5f

typedef unsigned int u32;
typedef unsigned long long u64;

// cvt two f32 -> packed bf16x2 (f0 -> low half, f1 -> high half)
#define CVT2BF(r, f0, f1) \
    asm("cvt.rn.bf16x2.f32 %0, %1, %2;" : "=r"(r) : "f"(f1), "f"(f0))

__device__ __forceinline__ void mma16816(float* d, const u32 a0, const u32 a1,
                                         const u32 a2, const u32 a3,
                                         const u32 b0, const u32 b1) {
    asm volatile(
        "mma.sync.aligned.m16n8k16.row.col.f32.bf16.bf16.f32 "
        "{%0,%1,%2,%3}, {%4,%5,%6,%7}, {%8,%9}, {%0,%1,%2,%3};"
        : "+f"(d[0]), "+f"(d[1]), "+f"(d[2]), "+f"(d[3])
        : "r"(a0), "r"(a1), "r"(a2), "r"(a3), "r"(b0), "r"(b1));
}

__device__ __forceinline__ float sel4(float a, float b, float c, float d, int s) {
    float r = (s == 0) ? a : ((s == 1) ? b : ((s == 2) ? c : d));
    return r;
}

__device__ float g_partials[128];
__device__ unsigned int g_count = 0;

__global__ __launch_bounds__(128) void bsde_mma(
    const float* __restrict__ y0, const float* __restrict__ Y0,
    const float* __restrict__ zW1, const float* __restrict__ zb1,
    const float* __restrict__ zW2, const float* __restrict__ zb2,
    const float* __restrict__ zW3, const float* __restrict__ zb3,
    const float* __restrict__ qW1, const float* __restrict__ qb1,
    const float* __restrict__ qW2, const float* __restrict__ qb2,
    const float* __restrict__ qW3, const float* __restrict__ qb3,
    const float* __restrict__ dW, const float* __restrict__ dZ,
    float* __restrict__ out)
{
    // W2S[m][half][pos]: pos = n*16 + ((kt ^ (n&3))<<2) + tq
    //   u64 = 4 bf16: {W2[16kt+2tq][n], [..+1], [..+8], [..+9]}
    __shared__ u64 W2S[2][2][1024];
    __shared__ float4 W1P[2][64];     // {W1t[n], W1y[n], b1[n], 0}
    __shared__ float4 W3P[2][64];     // z: {w3n0,w3n1,w3n2,0} ; q: {qw3n,0,0,0}
    __shared__ float  B2S[2][64];
    __shared__ float  B3S[2][4];
    __shared__ float4 scratch[2][4][32];
    __shared__ float  red[128];
    __shared__ int    is_last;

    const int tx = threadIdx.x;
    const int l  = tx & 31;
    const int w  = tx >> 5;
    const int g  = l >> 2;
    const int tq = l & 3;

    // ---------------- stage weights ----------------
    for (int idx = tx; idx < 4096; idx += 128) {
        int k = idx >> 6, n = idx & 63;
        int kt = k >> 4, r = k & 15;
        int tt, slot;
        if (r < 8) { tt = r >> 1; slot = r & 1; }
        else       { tt = (r - 8) >> 1; slot = 2 + (r & 1); }
        int pos = n * 16 + ((kt ^ (n & 3)) << 2) + tt;
        {
            float wv = zW2[idx];
            __nv_bfloat16 hi = __float2bfloat16_rn(wv);
            __nv_bfloat16 lo = __float2bfloat16_rn(wv - __bfloat162float(hi));
            ((__nv_bfloat16*)&W2S[0][0][pos])[slot] = hi;
            ((__nv_bfloat16*)&W2S[0][1][pos])[slot] = lo;
        }
        {
            float wv = qW2[idx];
            __nv_bfloat16 hi = __float2bfloat16_rn(wv);
            __nv_bfloat16 lo = __float2bfloat16_rn(wv - __bfloat162float(hi));
            ((__nv_bfloat16*)&W2S[1][0][pos])[slot] = hi;
            ((__nv_bfloat16*)&W2S[1][1][pos])[slot] = lo;
        }
    }
    if (tx < 64) {
        int n = tx;
        W1P[0][n] = make_float4(zW1[n], zW1[64 + n], zb1[n], 0.f);
        W1P[1][n] = make_float4(qW1[n], qW1[64 + n], qb1[n], 0.f);
        W3P[0][n] = make_float4(zW3[n * 3], zW3[n * 3 + 1], zW3[n * 3 + 2], 0.f);
        W3P[1][n] = make_float4(qW3[n], 0.f, 0.f, 0.f);
        B2S[0][n] = zb2[n];
        B2S[1][n] = qb2[n];
    }
    if (tx < 4) {
        B3S[0][tx] = (tx < 3) ? zb3[tx] : 0.f;
        B3S[1][tx] = (tx == 0) ? qb3[0] : 0.f;
    }
    __syncthreads();

    // ---------------- per-path state ----------------
    const int path = blockIdx.x * 128 + tx;   // lane l of warp w owns path base+l
    float y = y0[0], Yv = Y0[0], t = 0.f, loss = 0.f;
    const float* dWp = dW + path * 3;
    const float* dZp = dZ + path * 3;

    #pragma unroll 1
    for (int i = 0; i < NSTEPS; ++i) {
        float dw0 = dWp[0] * SQDT, dw1 = dWp[1] * SQDT, dw2 = dWp[2] * SQDT;
        float dz0 = dZp[0] * SQDT, dz1 = dZp[1] * SQDT, dz2 = dZp[2] * SQDT;
        dWp += NB * 3; dZp += NB * 3;

        // y value for the 4 row-slots this lane covers (rows g+8s)
        float ys0 = __shfl_sync(0xffffffffu, y, g, 32);
        float ys1 = __shfl_sync(0xffffffffu, y, g + 8, 32);
        float ys2 = __shfl_sync(0xffffffffu, y, g + 16, 32);
        float ys3 = __shfl_sync(0xffffffffu, y, g + 24, 32);
        float ysv[4] = {ys0, ys1, ys2, ys3};

        #pragma unroll 1
        for (int m = 0; m < 2; ++m) {
            // ---- layer 1 directly in A-fragment layout; bf16 hi/lo split ----
            u32 Ahi[4][2][4], Alo[4][2][4];   // [kt][e][s]
            #pragma unroll
            for (int kt = 0; kt < 4; ++kt) {
                #pragma unroll
                for (int e = 0; e < 2; ++e) {
                    int c0 = 16 * kt + 2 * tq + 8 * e;
                    float4 p0 = W1P[m][c0];
                    float4 p1 = W1P[m][c0 + 1];
                    float al0 = fmaf(t, p0.x, p0.z);
                    float al1 = fmaf(t, p1.x, p1.z);
                    #pragma unroll
                    for (int s = 0; s < 4; ++s) {
                        float h0 = fmaxf(fmaf(ysv[s], p0.y, al0), 0.f);
                        float h1 = fmaxf(fmaf(ysv[s], p1.y, al1), 0.f);
                        u32 hp; CVT2BF(hp, h0, h1);
                        float l0 = h0 - __uint_as_float(hp << 16);
                        float l1 = h1 - __uint_as_float(hp & 0xFFFF0000u);
                        u32 lp; CVT2BF(lp, l0, l1);
                        Ahi[kt][e][s] = hp;
                        Alo[kt][e][s] = lp;
                    }
                }
            }

            // ---- GEMM + fused epilogue ----
            float o[4][3];
            #pragma unroll
            for (int s = 0; s < 4; ++s) { o[s][0] = 0.f; o[s][1] = 0.f; o[s][2] = 0.f; }

            const u64* Wh = &W2S[m][0][0];
            const u64* Wl = &W2S[m][1][0];
            const int nb = g;                  // B-frag n (within tile) = g
            const int xk = nb & 3;

            #pragma unroll 1
            for (int nt = 0; nt < 8; ++nt) {
                float d0[4] = {0.f, 0.f, 0.f, 0.f};
                float d1[4] = {0.f, 0.f, 0.f, 0.f};
                int nfull = 8 * nt + nb;
                #pragma unroll
                for (int kt = 0; kt < 4; ++kt) {
                    int pos = nfull * 16 + (((kt ^ xk) & 3) << 2) + tq;
                    u64 bh = Wh[pos];
                    u64 bl = Wl[pos];
                    u32 bh0 = (u32)bh, bh1 = (u32)(bh >> 32);
                    u32 bl0 = (u32)bl, bl1 = (u32)(bl >> 32);
                    // mt = 0 (rows g, g+8)
                    mma16816(d0, Ahi[kt][0][0], Ahi[kt][0][1], Ahi[kt][1][0], Ahi[kt][1][1], bh0, bh1);
                    mma16816(d0, Ahi[kt][0][0], Ahi[kt][0][1], Ahi[kt][1][0], Ahi[kt][1][1], bl0, bl1);
                    mma16816(d0, Alo[kt][0][0], Alo[kt][0][1], Alo[kt][1][0], Alo[kt][1][1], bh0, bh1);
                    // mt = 1 (rows g+16, g+24)
                    mma16816(d1, Ahi[kt][0][2], Ahi[kt][0][3], Ahi[kt][1][2], Ahi[kt][1][3], bh0, bh1);
                    mma16816(d1, Ahi[kt][0][2], Ahi[kt][0][3], Ahi[kt][1][2], Ahi[kt][1][3], bl0, bl1);
                    mma16816(d1, Alo[kt][0][2], Alo[kt][0][3], Alo[kt][1][2], Alo[kt][1][3], bh0, bh1);
                }
                // epilogue for cols n0, n0+1 (this lane's D cols)
                int n0 = 8 * nt + 2 * tq;
                float b20 = B2S[m][n0], b21 = B2S[m][n0 + 1];
                float4 w30 = W3P[m][n0];
                float4 w31 = W3P[m][n0 + 1];
                // d0: {D[g][n0], D[g][n0+1], D[g+8][n0], D[g+8][n0+1]} -> slots 0,1
                // d1: rows g+16, g+24 -> slots 2,3
                #pragma unroll
                for (int half = 0; half < 2; ++half) {
                    const float* dd = half ? d1 : d0;
                    #pragma unroll
                    for (int rr = 0; rr < 2; ++rr) {
                        int s = 2 * half + rr;
                        float h0 = fmaxf(dd[2 * rr] + b20, 0.f);
                        float h1 = fmaxf(dd[2 * rr + 1] + b21, 0.f);
                        o[s][0] = fmaf(h0, w30.x, fmaf(h1, w31.x, o[s][0]));
                        o[s][1] = fmaf(h0, w30.y, fmaf(h1, w31.y, o[s][1]));
                        o[s][2] = fmaf(h0, w30.z, fmaf(h1, w31.z, o[s][2]));
                    }
                }
            }

            // quad reduction (lanes with same g hold disjoint col subsets)
            #pragma unroll
            for (int s = 0; s < 4; ++s) {
                #pragma unroll
                for (int j = 0; j < 3; ++j) {
                    float v = o[s][j];
                    v += __shfl_xor_sync(0xffffffffu, v, 1, 32);
                    v += __shfl_xor_sync(0xffffffffu, v, 2, 32);
                    o[s][j] = v;
                }
            }
            // this lane writes row g + 8*tq  (slot s = tq)
            float r0 = sel4(o[0][0], o[1][0], o[2][0], o[3][0], tq);
            float r1 = sel4(o[0][1], o[1][1], o[2][1], o[3][1], tq);
            float r2 = sel4(o[0][2], o[1][2], o[2][2], o[3][2], tq);
            __syncwarp();
            scratch[m][w][g + 8 * tq] = make_float4(r0, r1, r2, 0.f);
            __syncwarp();
        }

        // ---- gather this path's outputs ----
        float4 zo = scratch[0][w][l];
        float4 qo = scratch[1][w][l];
        float o0 = zo.x + B3S[0][0];
        float o1 = zo.y + B3S[0][1];
        float o2 = zo.z + B3S[0][2];
        float qv = qo.x + B3S[1][0];

        // ---- SDE / BSDE update (residual = z.dw - z.dz; Y cancels) ----
        float zdw = o0 * dw0 + o1 * dw1 + o2 * dw2;
        float zdz = o0 * dz0 + o1 * dz1 + o2 * dz2;
        float f = 0.5f * qv * qv;
        y  = y + qv * DTC + SIG0 * (dw0 + dw1 + dw2);
        Yv = Yv - f * DTC + zdw;
        float r = zdw - zdz;
        loss = fmaf(r, r, loss);
        t += DTC;
    }
    float term = Yv - y * y;
    loss = fmaf(term, term, loss);

    // ---------------- reduction ----------------
    red[tx] = loss;
    __syncthreads();
    #pragma unroll
    for (int s = 64; s > 0; s >>= 1) {
        if (tx < s) red[tx] += red[tx + s];
        __syncthreads();
    }
    if (tx == 0) {
        g_partials[blockIdx.x] = red[0];
        __threadfence();
        unsigned int prev = atomicAdd(&g_count, 1u);
        is_last = (prev == gridDim.x - 1) ? 1 : 0;
    }
    __syncthreads();
    if (is_last) {
        __threadfence();
        red[tx] = g_partials[tx];      // gridDim.x == blockDim.x == 128
        __syncthreads();
        #pragma unroll
        for (int s = 64; s > 0; s >>= 1) {
            if (tx < s) red[tx] += red[tx + s];
            __syncthreads();
        }
        if (tx == 0) {
            out[0] = red[0] * (1.0f / (float)NB);
            g_count = 0;               // reset for graph replay
        }
    }
}

extern "C" void kernel_launch(void* const* d_in, const int* in_sizes, int n_in,
                              void* d_out, int out_size)
{
    const float* y0  = (const float*)d_in[0];
    const float* Y0  = (const float*)d_in[1];
    const float* zW1 = (const float*)d_in[2];
    const float* zb1 = (const float*)d_in[3];
    const float* zW2 = (const float*)d_in[4];
    const float* zb2 = (const float*)d_in[5];
    const float* zW3 = (const float*)d_in[6];
    const float* zb3 = (const float*)d_in[7];
    const float* qW1 = (const float*)d_in[8];
    const float* qb1 = (const float*)d_in[9];
    const float* qW2 = (const float*)d_in[10];
    const float* qb2 = (const float*)d_in[11];
    const float* qW3 = (const float*)d_in[12];
    const float* qb3 = (const float*)d_in[13];
    const float* dW  = (const float*)d_in[14];
    const float* dZ  = (const float*)d_in[15];

    bsde_mma<<<128, 128>>>(y0, Y0, zW1, zb1, zW2, zb2, zW3, zb3,
                           qW1, qb1, qW2, qb2, qW3, qb3, dW, dZ,
                           (float*)d_out);
}

// round 8
// speedup vs baseline: 3.3744x; 1.5041x over previous
#include <cuda_runtime.h>
#include <cuda_bf16.h>

#define NB 16384
#define NSTEPS 100
#define DTC 0.01f
#define SQDT 0.1f
#define SIG0 0.5f

typedef unsigned int u32;
typedef unsigned long long u64;

// cvt two f32 -> packed bf16x2 (f0 -> low half, f1 -> high half)
#define CVT2BF(r, f0, f1) \
    asm("cvt.rn.bf16x2.f32 %0, %1, %2;" : "=r"(r) : "f"(f1), "f"(f0))

__device__ __forceinline__ void mma16816(float* d, const u32 a0, const u32 a1,
                                         const u32 a2, const u32 a3,
                                         const u32 b0, const u32 b1) {
    asm volatile(
        "mma.sync.aligned.m16n8k16.row.col.f32.bf16.bf16.f32 "
        "{%0,%1,%2,%3}, {%4,%5,%6,%7}, {%8,%9}, {%0,%1,%2,%3};"
        : "+f"(d[0]), "+f"(d[1]), "+f"(d[2]), "+f"(d[3])
        : "r"(a0), "r"(a1), "r"(a2), "r"(a3), "r"(b0), "r"(b1));
}

__device__ __forceinline__ float sel4(float a, float b, float c, float d, int s) {
    float r = (s == 0) ? a : ((s == 1) ? b : ((s == 2) ? c : d));
    return r;
}

__device__ float g_partials[128];
__device__ unsigned int g_count = 0;

__global__ __launch_bounds__(128) void bsde_mma(
    const float* __restrict__ y0, const float* __restrict__ Y0,
    const float* __restrict__ zW1, const float* __restrict__ zb1,
    const float* __restrict__ zW2, const float* __restrict__ zb2,
    const float* __restrict__ zW3, const float* __restrict__ zb3,
    const float* __restrict__ qW1, const float* __restrict__ qb1,
    const float* __restrict__ qW2, const float* __restrict__ qb2,
    const float* __restrict__ qW3, const float* __restrict__ qb3,
    const float* __restrict__ dW, const float* __restrict__ dZ,
    float* __restrict__ out)
{
    // W2S[m][half][pos]: pos = n*16 + ((kt ^ (n&3))<<2) + tq
    //   u64 = 4 bf16: {W2[16kt+2tq][n], [..+1], [..+8], [..+9]}
    __shared__ u64 W2S[2][2][1024];
    __shared__ float4 W1P[2][64];     // {W1t[n], W1y[n], b1[n], 0}
    __shared__ float4 W3P[2][64];     // z: {w3n0,w3n1,w3n2,0} ; q: {qw3n,0,0,0}
    __shared__ float  B2S[2][64];
    __shared__ float  B3S[2][4];
    __shared__ float4 scratch[2][4][32];
    __shared__ float  red[128];
    __shared__ int    is_last;

    const int tx = threadIdx.x;
    const int l  = tx & 31;
    const int w  = tx >> 5;
    const int g  = l >> 2;
    const int tq = l & 3;

    // ---------------- stage weights ----------------
    for (int idx = tx; idx < 4096; idx += 128) {
        int k = idx >> 6, n = idx & 63;
        int kt = k >> 4, r = k & 15;
        int tt, slot;
        if (r < 8) { tt = r >> 1; slot = r & 1; }
        else       { tt = (r - 8) >> 1; slot = 2 + (r & 1); }
        int pos = n * 16 + ((kt ^ (n & 3)) << 2) + tt;
        {
            float wv = zW2[idx];
            __nv_bfloat16 hi = __float2bfloat16_rn(wv);
            __nv_bfloat16 lo = __float2bfloat16_rn(wv - __bfloat162float(hi));
            ((__nv_bfloat16*)&W2S[0][0][pos])[slot] = hi;
            ((__nv_bfloat16*)&W2S[0][1][pos])[slot] = lo;
        }
        {
            float wv = qW2[idx];
            __nv_bfloat16 hi = __float2bfloat16_rn(wv);
            __nv_bfloat16 lo = __float2bfloat16_rn(wv - __bfloat162float(hi));
            ((__nv_bfloat16*)&W2S[1][0][pos])[slot] = hi;
            ((__nv_bfloat16*)&W2S[1][1][pos])[slot] = lo;
        }
    }
    if (tx < 64) {
        int n = tx;
        W1P[0][n] = make_float4(zW1[n], zW1[64 + n], zb1[n], 0.f);
        W1P[1][n] = make_float4(qW1[n], qW1[64 + n], qb1[n], 0.f);
        W3P[0][n] = make_float4(zW3[n * 3], zW3[n * 3 + 1], zW3[n * 3 + 2], 0.f);
        W3P[1][n] = make_float4(qW3[n], 0.f, 0.f, 0.f);
        B2S[0][n] = zb2[n];
        B2S[1][n] = qb2[n];
    }
    if (tx < 4) {
        B3S[0][tx] = (tx < 3) ? zb3[tx] : 0.f;
        B3S[1][tx] = (tx == 0) ? qb3[0] : 0.f;
    }
    __syncthreads();

    // ---------------- per-path state ----------------
    const int path = blockIdx.x * 128 + tx;   // lane l of warp w owns path base+l
    float y = y0[0], Yv = Y0[0], t = 0.f, loss = 0.f;
    const float* dWp = dW + path * 3;
    const float* dZp = dZ + path * 3;

    #pragma unroll 1
    for (int i = 0; i < NSTEPS; ++i) {
        float dw0 = dWp[0] * SQDT, dw1 = dWp[1] * SQDT, dw2 = dWp[2] * SQDT;
        float dz0 = dZp[0] * SQDT, dz1 = dZp[1] * SQDT, dz2 = dZp[2] * SQDT;
        dWp += NB * 3; dZp += NB * 3;

        // y value for the 4 row-slots this lane covers (rows g+8s)
        float ys0 = __shfl_sync(0xffffffffu, y, g, 32);
        float ys1 = __shfl_sync(0xffffffffu, y, g + 8, 32);
        float ys2 = __shfl_sync(0xffffffffu, y, g + 16, 32);
        float ys3 = __shfl_sync(0xffffffffu, y, g + 24, 32);
        float ysv[4] = {ys0, ys1, ys2, ys3};

        #pragma unroll 1
        for (int m = 0; m < 2; ++m) {
            // ---- layer 1 directly in A-fragment layout; bf16 hi/lo split ----
            u32 Ahi[4][2][4], Alo[4][2][4];   // [kt][e][s]
            #pragma unroll
            for (int kt = 0; kt < 4; ++kt) {
                #pragma unroll
                for (int e = 0; e < 2; ++e) {
                    int c0 = 16 * kt + 2 * tq + 8 * e;
                    float4 p0 = W1P[m][c0];
                    float4 p1 = W1P[m][c0 + 1];
                    float al0 = fmaf(t, p0.x, p0.z);
                    float al1 = fmaf(t, p1.x, p1.z);
                    #pragma unroll
                    for (int s = 0; s < 4; ++s) {
                        float h0 = fmaxf(fmaf(ysv[s], p0.y, al0), 0.f);
                        float h1 = fmaxf(fmaf(ysv[s], p1.y, al1), 0.f);
                        u32 hp; CVT2BF(hp, h0, h1);
                        float l0 = h0 - __uint_as_float(hp << 16);
                        float l1 = h1 - __uint_as_float(hp & 0xFFFF0000u);
                        u32 lp; CVT2BF(lp, l0, l1);
                        Ahi[kt][e][s] = hp;
                        Alo[kt][e][s] = lp;
                    }
                }
            }

            // ---- GEMM: kt-outer, per-nt persistent accumulators (16 indep chains) ----
            float dacc[8][8];   // [nt][half*4 + idx]
            #pragma unroll
            for (int nt = 0; nt < 8; ++nt)
                #pragma unroll
                for (int j = 0; j < 8; ++j) dacc[nt][j] = 0.f;

            const u64* Wh = &W2S[m][0][0];
            const u64* Wl = &W2S[m][1][0];
            const int nb = g;                  // B-frag n (within tile) = g
            const int xk = nb & 3;

            #pragma unroll
            for (int kt = 0; kt < 4; ++kt) {
                #pragma unroll
                for (int nt = 0; nt < 8; ++nt) {
                    int nfull = 8 * nt + nb;
                    int pos = nfull * 16 + (((kt ^ xk) & 3) << 2) + tq;
                    u64 bh = Wh[pos];
                    u64 bl = Wl[pos];
                    u32 bh0 = (u32)bh, bh1 = (u32)(bh >> 32);
                    u32 bl0 = (u32)bl, bl1 = (u32)(bl >> 32);
                    float* d0 = &dacc[nt][0];
                    float* d1 = &dacc[nt][4];
                    // rows g, g+8
                    mma16816(d0, Ahi[kt][0][0], Ahi[kt][0][1], Ahi[kt][1][0], Ahi[kt][1][1], bh0, bh1);
                    mma16816(d0, Ahi[kt][0][0], Ahi[kt][0][1], Ahi[kt][1][0], Ahi[kt][1][1], bl0, bl1);
                    mma16816(d0, Alo[kt][0][0], Alo[kt][0][1], Alo[kt][1][0], Alo[kt][1][1], bh0, bh1);
                    // rows g+16, g+24
                    mma16816(d1, Ahi[kt][0][2], Ahi[kt][0][3], Ahi[kt][1][2], Ahi[kt][1][3], bh0, bh1);
                    mma16816(d1, Ahi[kt][0][2], Ahi[kt][0][3], Ahi[kt][1][2], Ahi[kt][1][3], bl0, bl1);
                    mma16816(d1, Alo[kt][0][2], Alo[kt][0][3], Alo[kt][1][2], Alo[kt][1][3], bh0, bh1);
                }
            }

            // ---- fused epilogue over nt tiles ----
            float o[4][3];
            #pragma unroll
            for (int s = 0; s < 4; ++s) { o[s][0] = 0.f; o[s][1] = 0.f; o[s][2] = 0.f; }

            #pragma unroll
            for (int nt = 0; nt < 8; ++nt) {
                int n0 = 8 * nt + 2 * tq;
                float b20 = B2S[m][n0], b21 = B2S[m][n0 + 1];
                float4 w30 = W3P[m][n0];
                float4 w31 = W3P[m][n0 + 1];
                #pragma unroll
                for (int half = 0; half < 2; ++half) {
                    const float* dd = &dacc[nt][half * 4];
                    #pragma unroll
                    for (int rr = 0; rr < 2; ++rr) {
                        int s = 2 * half + rr;
                        float h0 = fmaxf(dd[2 * rr] + b20, 0.f);
                        float h1 = fmaxf(dd[2 * rr + 1] + b21, 0.f);
                        o[s][0] = fmaf(h0, w30.x, fmaf(h1, w31.x, o[s][0]));
                        o[s][1] = fmaf(h0, w30.y, fmaf(h1, w31.y, o[s][1]));
                        o[s][2] = fmaf(h0, w30.z, fmaf(h1, w31.z, o[s][2]));
                    }
                }
            }

            // quad reduction (lanes with same g hold disjoint col subsets)
            #pragma unroll
            for (int s = 0; s < 4; ++s) {
                #pragma unroll
                for (int j = 0; j < 3; ++j) {
                    float v = o[s][j];
                    v += __shfl_xor_sync(0xffffffffu, v, 1, 32);
                    v += __shfl_xor_sync(0xffffffffu, v, 2, 32);
                    o[s][j] = v;
                }
            }
            // this lane writes row g + 8*tq  (slot s = tq)
            float r0 = sel4(o[0][0], o[1][0], o[2][0], o[3][0], tq);
            float r1 = sel4(o[0][1], o[1][1], o[2][1], o[3][1], tq);
            float r2 = sel4(o[0][2], o[1][2], o[2][2], o[3][2], tq);
            __syncwarp();
            scratch[m][w][g + 8 * tq] = make_float4(r0, r1, r2, 0.f);
            __syncwarp();
        }

        // ---- gather this path's outputs ----
        float4 zo = scratch[0][w][l];
        float4 qo = scratch[1][w][l];
        float o0 = zo.x + B3S[0][0];
        float o1 = zo.y + B3S[0][1];
        float o2 = zo.z + B3S[0][2];
        float qv = qo.x + B3S[1][0];

        // ---- SDE / BSDE update (residual = z.dw - z.dz; Y cancels) ----
        float zdw = o0 * dw0 + o1 * dw1 + o2 * dw2;
        float zdz = o0 * dz0 + o1 * dz1 + o2 * dz2;
        float f = 0.5f * qv * qv;
        y  = y + qv * DTC + SIG0 * (dw0 + dw1 + dw2);
        Yv = Yv - f * DTC + zdw;
        float r = zdw - zdz;
        loss = fmaf(r, r, loss);
        t += DTC;
    }
    float term = Yv - y * y;
    loss = fmaf(term, term, loss);

    // ---------------- reduction ----------------
    red[tx] = loss;
    __syncthreads();
    #pragma unroll
    for (int s = 64; s > 0; s >>= 1) {
        if (tx < s) red[tx] += red[tx + s];
        __syncthreads();
    }
    if (tx == 0) {
        g_partials[blockIdx.x] = red[0];
        __threadfence();
        unsigned int prev = atomicAdd(&g_count, 1u);
        is_last = (prev == gridDim.x - 1) ? 1 : 0;
    }
    __syncthreads();
    if (is_last) {
        __threadfence();
        red[tx] = g_partials[tx];      // gridDim.x == blockDim.x == 128
        __syncthreads();
        #pragma unroll
        for (int s = 64; s > 0; s >>= 1) {
            if (tx < s) red[tx] += red[tx + s];
            __syncthreads();
        }
        if (tx == 0) {
            out[0] = red[0] * (1.0f / (float)NB);
            g_count = 0;               // reset for graph replay
        }
    }
}

extern "C" void kernel_launch(void* const* d_in, const int* in_sizes, int n_in,
                              void* d_out, int out_size)
{
    const float* y0  = (const float*)d_in[0];
    const float* Y0  = (const float*)d_in[1];
    const float* zW1 = (const float*)d_in[2];
    const float* zb1 = (const float*)d_in[3];
    const float* zW2 = (const float*)d_in[4];
    const float* zb2 = (const float*)d_in[5];
    const float* zW3 = (const float*)d_in[6];
    const float* zb3 = (const float*)d_in[7];
    const float* qW1 = (const float*)d_in[8];
    const float* qb1 = (const float*)d_in[9];
    const float* qW2 = (const float*)d_in[10];
    const float* qb2 = (const float*)d_in[11];
    const float* qW3 = (const float*)d_in[12];
    const float* qb3 = (const float*)d_in[13];
    const float* dW  = (const float*)d_in[14];
    const float* dZ  = (const float*)d_in[15];

    bsde_mma<<<128, 128>>>(y0, Y0, zW1, zb1, zW2, zb2, zW3, zb3,
                           qW1, qb1, qW2, qb2, qW3, qb3, dW, dZ,
                           (float*)d_out);
}